// round 6
// baseline (speedup 1.0000x reference)
#include <cuda_runtime.h>
#include <cstdint>
#include <cstddef>

// Problem constants
#define Bsz 8
#define Hn  16
#define Nn  4096
#define DHn 64
#define Kn  128
#define Dn  1024

// Device scratch (no allocs allowed)
__device__ float         g_kp[Bsz * Kn * Dn];       // 4 MB projected keys
__device__ float         g_vp[Bsz * Kn * Dn];       // 4 MB projected values
__device__ unsigned char g_P8h[2 * Kn * Nn];        // P^T hi s8 limb [w][k][n]
__device__ unsigned char g_P8l[2 * Kn * Nn];        // P^T lo s8 limb

typedef unsigned long long u64;

// fixed-point scales
#define SCALE_P 262144.0f     // 2^18 (|p| <= 0.0884 -> |v| <= 23173)
#define SCALE_X 4096.0f       // 2^12 (|x| <= 8 covered; clamped)
#define INV_S   (1.0f / (262144.0f * 4096.0f))

// ---------------------------------------------------------------------------
// helpers
// ---------------------------------------------------------------------------
__device__ __forceinline__ uint32_t cvt2bf(float hi_elem, float lo_elem) {
    uint32_t r;
    asm("cvt.rn.bf16x2.f32 %0, %1, %2;" : "=r"(r) : "f"(hi_elem), "f"(lo_elem));
    return r;
}
__device__ __forceinline__ float bflo_f(uint32_t p) { return __uint_as_float(p << 16); }
__device__ __forceinline__ float bfhi_f(uint32_t p) { return __uint_as_float(p & 0xffff0000u); }

#define SWZ128(x) ((x) ^ (((x) >> 3) & 0x70))
#define SWZ256(x) ((x) ^ (((x) >> 4) & 0x70))

#define LDSM4(r, a) \
    asm volatile("ldmatrix.sync.aligned.m8n8.x4.shared.b16 {%0,%1,%2,%3}, [%4];" \
        : "=r"((r)[0]), "=r"((r)[1]), "=r"((r)[2]), "=r"((r)[3]) : "r"(a))
#define LDSM4T(r, a) \
    asm volatile("ldmatrix.sync.aligned.m8n8.x4.trans.shared.b16 {%0,%1,%2,%3}, [%4];" \
        : "=r"((r)[0]), "=r"((r)[1]), "=r"((r)[2]), "=r"((r)[3]) : "r"(a))
#define MMA_BF16(c, a, b0v, b1v) \
    asm volatile("mma.sync.aligned.m16n8k16.row.col.f32.bf16.bf16.f32 " \
        "{%0,%1,%2,%3}, {%4,%5,%6,%7}, {%8,%9}, {%0,%1,%2,%3};" \
        : "+f"((c)[0]), "+f"((c)[1]), "+f"((c)[2]), "+f"((c)[3]) \
        : "r"((a)[0]), "r"((a)[1]), "r"((a)[2]), "r"((a)[3]), "r"(b0v), "r"(b1v))
#define MMA_S8(c, a, b0v, b1v) \
    asm volatile("mma.sync.aligned.m16n8k32.row.col.s32.s8.s8.s32 " \
        "{%0,%1,%2,%3}, {%4,%5,%6,%7}, {%8,%9}, {%0,%1,%2,%3};" \
        : "+r"((c)[0]), "+r"((c)[1]), "+r"((c)[2]), "+r"((c)[3]) \
        : "r"((a)[0]), "r"((a)[1]), "r"((a)[2]), "r"((a)[3]), "r"(b0v), "r"(b1v))

__device__ __forceinline__ uint32_t smem_u32(const void* p) {
    uint32_t a;
    asm("{ .reg .u64 t; cvta.to.shared.u64 t, %1; cvt.u32.u64 %0, t; }" : "=r"(a) : "l"(p));
    return a;
}

// split a float4 (optionally scaled) into hi/lo bf16x2 pairs (attn kernel)
__device__ __forceinline__ void split4(float4 v, float s, uint2& h, uint2& l) {
    v.x *= s; v.y *= s; v.z *= s; v.w *= s;
    uint32_t h01 = cvt2bf(v.y, v.x);
    uint32_t h23 = cvt2bf(v.w, v.z);
    float h0 = bflo_f(h01), h1 = bfhi_f(h01);
    float h2 = bflo_f(h23), h3 = bfhi_f(h23);
    uint32_t l01 = cvt2bf(v.y - h1, v.x - h0);
    uint32_t l23 = cvt2bf(v.w - h3, v.z - h2);
    h = make_uint2(h01, h23);
    l = make_uint2(l01, l23);
}

// fixed-point 2-limb split, both limbs signed s8
__device__ __forceinline__ void fxsplit(float x, float S, int clampv, int& hi, int& lo) {
    int v = __float2int_rn(x * S);
    v = max(-clampv, min(clampv, v));
    hi = (v + 128) >> 8;
    lo = v - (hi << 8);
}
__device__ __forceinline__ uint32_t pack4(int b0, int b1, int b2, int b3) {
    return (uint32_t)(b0 & 0xff) | ((uint32_t)(b1 & 0xff) << 8) |
           ((uint32_t)(b2 & 0xff) << 16) | ((uint32_t)(b3 & 0xff) << 24);
}

// ============================================================================
// Kernel 0: transpose P [4096 n][128 k] -> fixed-point limbs [w][k][n] (s8)
// ============================================================================
__global__ void __launch_bounds__(256) ptrans_kernel(
    const float* __restrict__ pk, const float* __restrict__ pv)
{
    __shared__ float sT[128][33];
    const int t  = threadIdx.x;
    const int n0 = blockIdx.x * 32;
    const int w  = blockIdx.y;
    const float* __restrict__ P = w ? pv : pk;

    #pragma unroll
    for (int i = 0; i < 16; i++) {
        int idx = t + 256 * i;
        int r = idx >> 7, c = idx & 127;
        sT[c][r] = P[(size_t)(n0 + r) * Kn + c];
    }
    __syncthreads();

    unsigned char* __restrict__ oh = g_P8h + (size_t)w * Kn * Nn;
    unsigned char* __restrict__ ol = g_P8l + (size_t)w * Kn * Nn;
    #pragma unroll
    for (int it = 0; it < 4; it++) {
        int idx = t + 256 * it;
        int k = idx >> 3, q = idx & 7;                // n quad q -> n = n0 + q*4
        int h[4], l[4];
        #pragma unroll
        for (int j = 0; j < 4; j++)
            fxsplit(sT[k][q * 4 + j], SCALE_P, 32639, h[j], l[j]);
        size_t o = (size_t)k * Nn + n0 + q * 4;
        *(uint32_t*)&oh[o] = pack4(h[0], h[1], h[2], h[3]);
        *(uint32_t*)&ol[o] = pack4(l[0], l[1], l[2], l[3]);
    }
}

// ============================================================================
// Kernel 1: IMMA fixed-point projection.
//   C[k=128, d=128-slice] = sum_n PT[k][n] * X[n][d]
// Grid (dt=8, b=8, w=2) = 128 CTAs; 512 threads (16 warps: 4 m x 4 d).
// smem per stage (32 KB):
//   A: 128 k-rows x 128 B  (hi bytes [0,64) | lo bytes [64,128)),  SWZ128
//   B: 128 d-rows x 128 B  (X^T: hi n-bytes [0,64) | lo [64,128)), SWZ128
// Inner: per 64-n chunk: 2 k32-steps; passes hi*hi -> C1, hi*lo+lo*hi -> C2.
// ============================================================================
#define QJ_SA 0
#define QJ_SB 16384
#define QJ_STAGE 32768
#define QJ_SMEM (2 * QJ_STAGE)

__global__ void __launch_bounds__(512, 1) proj_imma_kernel(
    const float* __restrict__ keys, const float* __restrict__ values)
{
    const int dt = blockIdx.x;    // 0..7
    const int b  = blockIdx.y;    // 0..7
    const int w  = blockIdx.z;    // 0..1

    const float* __restrict__ X = (w ? values : keys) + (size_t)b * Nn * Dn + dt * 128;
    const unsigned char* __restrict__ P8h = g_P8h + (size_t)w * Kn * Nn;
    const unsigned char* __restrict__ P8l = g_P8l + (size_t)w * Kn * Nn;
    float* __restrict__ Cg = (w ? g_vp : g_kp) + (size_t)b * Kn * Dn + dt * 128;

    extern __shared__ __align__(1024) unsigned char dsm[];
    const uint32_t sbase = smem_u32(dsm);

    const int tid  = threadIdx.x;
    const int wid  = tid >> 5, lane = tid & 31;
    const int warp_m = (wid >> 2) * 32;   // k-row base
    const int warp_d = (wid & 3) * 32;    // d base

    int c1[2][4][4], c2[2][4][4];
    #pragma unroll
    for (int i = 0; i < 2; i++)
        #pragma unroll
        for (int j = 0; j < 4; j++)
            #pragma unroll
            for (int q = 0; q < 4; q++) { c1[i][j][q] = 0; c2[i][j][q] = 0; }

    // prefetch registers: A = 1 hi uint4 + 1 lo uint4; B = 4 float4 (4 n x 4 d)
    uint4  pAh, pAl;
    float4 pB[4];
    const int arow = tid >> 2, ac16 = tid & 3;       // A: 512 units of 16 B (hi)
    const int dg = tid & 31, ng = tid >> 5;          // B: d-group (4 d), n-group (4 n)

    {
        size_t o = (size_t)arow * Nn + ac16 * 16;
        pAh = *(const uint4*)&P8h[o];
        pAl = *(const uint4*)&P8l[o];
        #pragma unroll
        for (int i = 0; i < 4; i++)
            pB[i] = *(const float4*)&X[(size_t)(ng * 4 + i) * Dn + dg * 4];
    }

    for (int c = 0; c < 64; ++c) {
        unsigned char* st = dsm + (c & 1) * QJ_STAGE;

        // ---- STS A (precomputed limbs, 16B copies) ----
        {
            uint32_t offh = SWZ128((uint32_t)(arow * 128 + ac16 * 16));
            uint32_t offl = SWZ128((uint32_t)(arow * 128 + 64 + ac16 * 16));
            *(uint4*)(st + QJ_SA + offh) = pAh;
            *(uint4*)(st + QJ_SA + offl) = pAl;
        }
        // ---- STS B: quantize + byte-transpose to [d][n] ----
        {
            int h[4][4], l[4][4];
            #pragma unroll
            for (int i = 0; i < 4; i++) {
                fxsplit(pB[i].x, SCALE_X, 32639, h[i][0], l[i][0]);
                fxsplit(pB[i].y, SCALE_X, 32639, h[i][1], l[i][1]);
                fxsplit(pB[i].z, SCALE_X, 32639, h[i][2], l[i][2]);
                fxsplit(pB[i].w, SCALE_X, 32639, h[i][3], l[i][3]);
            }
            #pragma unroll
            for (int j = 0; j < 4; j++) {
                int drow = dg * 4 + j;
                uint32_t hb = pack4(h[0][j], h[1][j], h[2][j], h[3][j]);
                uint32_t lb = pack4(l[0][j], l[1][j], l[2][j], l[3][j]);
                *(uint32_t*)(st + QJ_SB + SWZ128((uint32_t)(drow * 128 + ng * 4))) = hb;
                *(uint32_t*)(st + QJ_SB + SWZ128((uint32_t)(drow * 128 + 64 + ng * 4))) = lb;
            }
        }
        __syncthreads();

        // ---- prefetch chunk c+1 ----
        if (c < 63) {
            int nb = (c + 1) * 64;
            size_t o = (size_t)arow * Nn + nb + ac16 * 16;
            pAh = *(const uint4*)&P8h[o];
            pAl = *(const uint4*)&P8l[o];
            #pragma unroll
            for (int i = 0; i < 4; i++)
                pB[i] = *(const float4*)&X[(size_t)(nb + ng * 4 + i) * Dn + dg * 4];
        }

        // ---- compute: 2 k32-steps over the 64-n chunk ----
        const uint32_t sA = sbase + (c & 1) * QJ_STAGE + QJ_SA;
        const uint32_t sB = sbase + (c & 1) * QJ_STAGE + QJ_SB;
        #pragma unroll
        for (int ks = 0; ks < 2; ks++) {
            uint32_t ah[2][4], al[2][4];
            #pragma unroll
            for (int mi = 0; mi < 2; mi++) {
                int row = warp_m + mi * 16 + (lane & 15);
                uint32_t cb = ks * 32 + (lane >> 4) * 16;
                LDSM4(ah[mi], sA + SWZ128((uint32_t)(row * 128 + cb)));
                LDSM4(al[mi], sA + SWZ128((uint32_t)(row * 128 + 64 + cb)));
            }
            #pragma unroll
            for (int jj = 0; jj < 2; jj++) {
                int rowb = warp_d + jj * 16 + (lane & 15);
                uint32_t cb = ks * 32 + (lane >> 4) * 16;
                uint32_t bh[4], bl[4];
                LDSM4(bh, sB + SWZ128((uint32_t)(rowb * 128 + cb)));
                LDSM4(bl, sB + SWZ128((uint32_t)(rowb * 128 + 64 + cb)));
                // non-trans B pairing: tile(2jj)=(r0,r2), tile(2jj+1)=(r1,r3)
                #pragma unroll
                for (int mi = 0; mi < 2; mi++) {
                    int* d10 = c1[mi][jj * 2];
                    int* d20 = c2[mi][jj * 2];
                    MMA_S8(d10, ah[mi], bh[0], bh[2]);
                    MMA_S8(d20, ah[mi], bl[0], bl[2]);
                    MMA_S8(d20, al[mi], bh[0], bh[2]);
                    int* d11 = c1[mi][jj * 2 + 1];
                    int* d21 = c2[mi][jj * 2 + 1];
                    MMA_S8(d11, ah[mi], bh[1], bh[3]);
                    MMA_S8(d21, ah[mi], bl[1], bl[3]);
                    MMA_S8(d21, al[mi], bh[1], bh[3]);
                }
            }
        }
        __syncthreads();
    }

    // ---- epilogue: combine limbs, store ----
    const float wHI = 65536.0f * INV_S;
    const float wLO = 256.0f * INV_S;
    #pragma unroll
    for (int mi = 0; mi < 2; mi++) {
        #pragma unroll
        for (int t2 = 0; t2 < 4; t2++) {
            int row = warp_m + mi * 16 + (lane >> 2);
            int col = warp_d + t2 * 8 + (lane & 3) * 2;
            float f0 = fmaf((float)c1[mi][t2][0], wHI, (float)c2[mi][t2][0] * wLO);
            float f1 = fmaf((float)c1[mi][t2][1], wHI, (float)c2[mi][t2][1] * wLO);
            float f2 = fmaf((float)c1[mi][t2][2], wHI, (float)c2[mi][t2][2] * wLO);
            float f3 = fmaf((float)c1[mi][t2][3], wHI, (float)c2[mi][t2][3] * wLO);
            *(float2*)&Cg[(size_t)row * Dn + col]       = make_float2(f0, f1);
            *(float2*)&Cg[(size_t)(row + 8) * Dn + col] = make_float2(f2, f3);
        }
    }
}

// ============================================================================
// Kernel 2: tensor-core attention (identical to round-5 passing version)
// ============================================================================
#define AT_QHI  0
#define AT_QLO  16384
#define AT_KHI  32768
#define AT_KLO  49152
#define AT_PHI  0
#define AT_PLO  32768
#define AT_VHI  65536
#define AT_VLO  81920
#define AT_SMAX 98304
#define AT_SSUM 99328
#define AT_SMEM 100352

__global__ void __launch_bounds__(256, 2) attn_mma_kernel(
    const float* __restrict__ qg, float* __restrict__ outg)
{
    const int nt = blockIdx.x;
    const int h  = blockIdx.y;
    const int b  = blockIdx.z;

    extern __shared__ __align__(1024) unsigned char smb[];
    const uint32_t sbase = smem_u32(smb);
    float* smax = (float*)(smb + AT_SMAX);
    float* ssum = (float*)(smb + AT_SSUM);

    const int tid  = threadIdx.x;
    const int wid  = tid >> 5, lane = tid & 31;
    const int g    = lane >> 2, tk = lane & 3;
    const int wm   = (wid >> 1) * 32;
    const int kh   = wid & 1;

    {
        const size_t qbase = ((size_t)b * Nn + (size_t)nt * 128) * Dn + h * 64;
        const size_t kbase = (size_t)b * Kn * Dn + h * 64;
        #pragma unroll
        for (int t = 0; t < 8; t++) {
            int idx = tid + 256 * t;
            int row = idx >> 4, c4 = idx & 15;
            size_t go = (size_t)row * Dn + c4 * 4;
            uint32_t off = SWZ128((uint32_t)(row * 128 + c4 * 8));
            uint2 hh, ll;
            split4(*(const float4*)&qg[qbase + go], 0.125f, hh, ll);
            *(uint2*)(smb + AT_QHI + off) = hh;
            *(uint2*)(smb + AT_QLO + off) = ll;
            split4(*(const float4*)&g_kp[kbase + go], 1.0f, hh, ll);
            *(uint2*)(smb + AT_KHI + off) = hh;
            *(uint2*)(smb + AT_KLO + off) = ll;
            split4(*(const float4*)&g_vp[kbase + go], 1.0f, hh, ll);
            *(uint2*)(smb + AT_VHI + off) = hh;
            *(uint2*)(smb + AT_VLO + off) = ll;
        }
    }
    __syncthreads();

    float acc[2][8][4];
    #pragma unroll
    for (int i = 0; i < 2; i++)
        #pragma unroll
        for (int j = 0; j < 8; j++)
            #pragma unroll
            for (int q = 0; q < 4; q++) acc[i][j][q] = 0.0f;

    {
        const int wk = kh * 64;
        #pragma unroll
        for (int ks = 0; ks < 4; ks++) {
            uint32_t ah[2][4], al[2][4];
            #pragma unroll
            for (int mi = 0; mi < 2; mi++) {
                uint32_t off = SWZ128((uint32_t)((wm + mi * 16 + (lane & 15)) * 128
                                                 + ks * 32 + (lane >> 4) * 16));
                LDSM4(ah[mi], sbase + AT_QHI + off);
                LDSM4(al[mi], sbase + AT_QLO + off);
            }
            #pragma unroll
            for (int jj = 0; jj < 4; jj++) {
                uint32_t offb = SWZ128((uint32_t)((wk + jj * 16 + (lane & 15)) * 128
                                                  + ks * 32 + (lane >> 4) * 16));
                uint32_t bh[4], bl[4];
                LDSM4(bh, sbase + AT_KHI + offb);
                LDSM4(bl, sbase + AT_KLO + offb);
                #pragma unroll
                for (int mi = 0; mi < 2; mi++) {
                    float* c0 = acc[mi][jj * 2];
                    MMA_BF16(c0, ah[mi], bh[0], bh[2]);
                    MMA_BF16(c0, ah[mi], bl[0], bl[2]);
                    MMA_BF16(c0, al[mi], bh[0], bh[2]);
                    float* c1v = acc[mi][jj * 2 + 1];
                    MMA_BF16(c1v, ah[mi], bh[1], bh[3]);
                    MMA_BF16(c1v, ah[mi], bl[1], bl[3]);
                    MMA_BF16(c1v, al[mi], bh[1], bh[3]);
                }
            }
        }
    }

    #pragma unroll
    for (int mi = 0; mi < 2; mi++) {
        #pragma unroll
        for (int h2 = 0; h2 < 2; h2++) {
            float m = acc[mi][0][h2 * 2];
            #pragma unroll
            for (int j = 0; j < 8; j++)
                m = fmaxf(m, fmaxf(acc[mi][j][h2 * 2], acc[mi][j][h2 * 2 + 1]));
            m = fmaxf(m, __shfl_xor_sync(0xffffffffu, m, 1));
            m = fmaxf(m, __shfl_xor_sync(0xffffffffu, m, 2));
            if (tk == 0) smax[(wm + mi * 16 + g + h2 * 8) * 2 + kh] = m;
        }
    }
    __syncthreads();

    #pragma unroll
    for (int mi = 0; mi < 2; mi++) {
        #pragma unroll
        for (int h2 = 0; h2 < 2; h2++) {
            int row = wm + mi * 16 + g + h2 * 8;
            float M = fmaxf(smax[row * 2], smax[row * 2 + 1]);
            float s = 0.0f;
            #pragma unroll
            for (int j = 0; j < 8; j++) {
                float x0 = __expf(acc[mi][j][h2 * 2]     - M);
                float x1 = __expf(acc[mi][j][h2 * 2 + 1] - M);
                s += x0 + x1;
                uint32_t hi = cvt2bf(x1, x0);
                float f0 = bflo_f(hi), f1 = bfhi_f(hi);
                uint32_t lo = cvt2bf(x1 - f1, x0 - f0);
                uint32_t off = SWZ256((uint32_t)(row * 256 + kh * 128 + j * 16 + tk * 4));
                *(uint32_t*)(smb + AT_PHI + off) = hi;
                *(uint32_t*)(smb + AT_PLO + off) = lo;
            }
            s += __shfl_xor_sync(0xffffffffu, s, 1);
            s += __shfl_xor_sync(0xffffffffu, s, 2);
            if (tk == 0) ssum[row * 2 + kh] = s;
        }
    }
    __syncthreads();

    float o[2][4][4];
    #pragma unroll
    for (int i = 0; i < 2; i++)
        #pragma unroll
        for (int j = 0; j < 4; j++)
            #pragma unroll
            for (int q = 0; q < 4; q++) o[i][j][q] = 0.0f;

    {
        const int wdh = kh * 32;
        #pragma unroll
        for (int ks = 0; ks < 8; ks++) {
            uint32_t ah[2][4], al[2][4];
            #pragma unroll
            for (int mi = 0; mi < 2; mi++) {
                uint32_t off = SWZ256((uint32_t)((wm + mi * 16 + (lane & 15)) * 256
                                                 + ks * 32 + (lane >> 4) * 16));
                LDSM4(ah[mi], sbase + AT_PHI + off);
                LDSM4(al[mi], sbase + AT_PLO + off);
            }
            #pragma unroll
            for (int g2 = 0; g2 < 2; g2++) {
                uint32_t offb = SWZ128((uint32_t)((ks * 16 + (lane & 15)) * 128
                                                  + wdh * 2 + g2 * 32 + (lane >> 4) * 16));
                uint32_t bh[4], bl[4];
                LDSM4T(bh, sbase + AT_VHI + offb);
                LDSM4T(bl, sbase + AT_VLO + offb);
                #pragma unroll
                for (int mi = 0; mi < 2; mi++) {
                    #pragma unroll
                    for (int jj = 0; jj < 2; jj++) {
                        float* cc = o[mi][g2 * 2 + jj];
                        MMA_BF16(cc, ah[mi], bh[jj * 2], bh[jj * 2 + 1]);
                        MMA_BF16(cc, ah[mi], bl[jj * 2], bl[jj * 2 + 1]);
                        MMA_BF16(cc, al[mi], bh[jj * 2], bh[jj * 2 + 1]);
                    }
                }
            }
        }
    }

    {
        const int wdh = kh * 32;
        const size_t obase = ((size_t)b * Nn + (size_t)nt * 128) * Dn + h * 64;
        #pragma unroll
        for (int mi = 0; mi < 2; mi++) {
            int r0 = wm + mi * 16 + g;
            int r1 = r0 + 8;
            float ri0 = 1.0f / (ssum[r0 * 2] + ssum[r0 * 2 + 1]);
            float ri1 = 1.0f / (ssum[r1 * 2] + ssum[r1 * 2 + 1]);
            #pragma unroll
            for (int j = 0; j < 4; j++) {
                int col = wdh + j * 8 + tk * 2;
                *(float2*)&outg[obase + (size_t)r0 * Dn + col] =
                    make_float2(o[mi][j][0] * ri0, o[mi][j][1] * ri0);
                *(float2*)&outg[obase + (size_t)r1 * Dn + col] =
                    make_float2(o[mi][j][2] * ri1, o[mi][j][3] * ri1);
            }
        }
    }
}

// ============================================================================
// Launch
// ============================================================================
extern "C" void kernel_launch(void* const* d_in, const int* in_sizes, int n_in,
                              void* d_out, int out_size)
{
    const float* q      = (const float*)d_in[0];
    const float* keys   = (const float*)d_in[1];
    const float* values = (const float*)d_in[2];
    const float* pk     = (const float*)d_in[3];
    const float* pv     = (const float*)d_in[4];
    float* out = (float*)d_out;

    cudaFuncSetAttribute(proj_imma_kernel,
                         cudaFuncAttributeMaxDynamicSharedMemorySize, QJ_SMEM);
    cudaFuncSetAttribute(attn_mma_kernel,
                         cudaFuncAttributeMaxDynamicSharedMemorySize, AT_SMEM);

    ptrans_kernel<<<dim3(Nn / 32, 2), 256>>>(pk, pv);
    proj_imma_kernel<<<dim3(8, Bsz, 2), 512, QJ_SMEM>>>(keys, values);
    attn_mma_kernel<<<dim3(Nn / 128, Hn, Bsz), 256, AT_SMEM>>>(q, out);
}

// round 8
// speedup vs baseline: 2.1570x; 2.1570x over previous
#include <cuda_runtime.h>
#include <cuda_fp16.h>
#include <cstdint>
#include <cstddef>

// Problem constants
#define Bsz 8
#define Hn  16
#define Nn  4096
#define DHn 64
#define Kn  128
#define Dn  1024

// Device scratch (no allocs allowed)
__device__ float    g_kp[Bsz * Kn * Dn];           // 4 MB projected keys
__device__ float    g_vp[Bsz * Kn * Dn];           // 4 MB projected values
__device__ uint32_t g_PTh[2 * Kn * (Nn / 2)];      // P^T hi f16 pairs [w][k][n/2]
__device__ uint32_t g_PTl[2 * Kn * (Nn / 2)];      // P^T lo f16 pairs

typedef unsigned long long u64;

// ---------------------------------------------------------------------------
// helpers (fp16 limbs)
// ---------------------------------------------------------------------------
// pack two f32 -> f16x2 (first operand -> upper 16 bits, second -> lower)
__device__ __forceinline__ uint32_t cvt2h(float hi_elem, float lo_elem) {
    uint32_t r;
    asm("cvt.rn.f16x2.f32 %0, %1, %2;" : "=r"(r) : "f"(hi_elem), "f"(lo_elem));
    return r;
}
__device__ __forceinline__ float f16lo(uint32_t p) {
    return __half2float(__ushort_as_half((unsigned short)(p & 0xffffu)));
}
__device__ __forceinline__ float f16hi(uint32_t p) {
    return __half2float(__ushort_as_half((unsigned short)(p >> 16)));
}

// swizzles: XOR 16B-unit index bits with low row bits (row stride 128B / 256B)
#define SWZ128(x) ((x) ^ (((x) >> 3) & 0x70))
#define SWZ256(x) ((x) ^ (((x) >> 4) & 0x70))

#define LDSM4(r, a) \
    asm volatile("ldmatrix.sync.aligned.m8n8.x4.shared.b16 {%0,%1,%2,%3}, [%4];" \
        : "=r"((r)[0]), "=r"((r)[1]), "=r"((r)[2]), "=r"((r)[3]) : "r"(a))
#define LDSM4T(r, a) \
    asm volatile("ldmatrix.sync.aligned.m8n8.x4.trans.shared.b16 {%0,%1,%2,%3}, [%4];" \
        : "=r"((r)[0]), "=r"((r)[1]), "=r"((r)[2]), "=r"((r)[3]) : "r"(a))
#define MMA_F16(c, a, b0v, b1v) \
    asm volatile("mma.sync.aligned.m16n8k16.row.col.f32.f16.f16.f32 " \
        "{%0,%1,%2,%3}, {%4,%5,%6,%7}, {%8,%9}, {%0,%1,%2,%3};" \
        : "+f"((c)[0]), "+f"((c)[1]), "+f"((c)[2]), "+f"((c)[3]) \
        : "r"((a)[0]), "r"((a)[1]), "r"((a)[2]), "r"((a)[3]), "r"(b0v), "r"(b1v))

__device__ __forceinline__ uint32_t smem_u32(const void* p) {
    uint32_t a;
    asm("{ .reg .u64 t; cvta.to.shared.u64 t, %1; cvt.u32.u64 %0, t; }" : "=r"(a) : "l"(p));
    return a;
}

// split a float4 (optionally scaled) into hi/lo f16x2 pairs
__device__ __forceinline__ void split4h(float4 v, float s, uint2& h, uint2& l) {
    v.x *= s; v.y *= s; v.z *= s; v.w *= s;
    uint32_t h01 = cvt2h(v.y, v.x);
    uint32_t h23 = cvt2h(v.w, v.z);
    float h0 = f16lo(h01), h1 = f16hi(h01);
    float h2 = f16lo(h23), h3 = f16hi(h23);
    uint32_t l01 = cvt2h(v.y - h1, v.x - h0);
    uint32_t l23 = cvt2h(v.w - h3, v.z - h2);
    h = make_uint2(h01, h23);
    l = make_uint2(l01, l23);
}

// ============================================================================
// Kernel 0: transpose P [4096 n][128 k] -> split-f16 PT [w][128 k][4096 n]
// ============================================================================
__global__ void __launch_bounds__(256) ptrans_kernel(
    const float* __restrict__ pk, const float* __restrict__ pv)
{
    __shared__ float sT[128][33];
    const int t  = threadIdx.x;
    const int n0 = blockIdx.x * 32;
    const int w  = blockIdx.y;
    const float* __restrict__ P = w ? pv : pk;

    #pragma unroll
    for (int i = 0; i < 16; i++) {
        int idx = t + 256 * i;
        int r = idx >> 7, c = idx & 127;
        sT[c][r] = P[(size_t)(n0 + r) * Kn + c];
    }
    __syncthreads();

    uint32_t* __restrict__ oh = g_PTh + (size_t)w * Kn * (Nn / 2);
    uint32_t* __restrict__ ol = g_PTl + (size_t)w * Kn * (Nn / 2);
    #pragma unroll
    for (int i = 0; i < 8; i++) {
        int idx = t + 256 * i;
        int k = idx >> 4, pr = idx & 15;
        float x0 = sT[k][2 * pr], x1 = sT[k][2 * pr + 1];
        uint32_t h = cvt2h(x1, x0);
        float h0 = f16lo(h), h1 = f16hi(h);
        uint32_t l = cvt2h(x1 - h1, x0 - h0);
        size_t o = (size_t)k * (Nn / 2) + (n0 >> 1) + pr;
        oh[o] = h;
        ol[o] = l;
    }
}

// ============================================================================
// Kernel 1: mma.sync f16-split projection (3-pass; structure = round-4/5)
// ============================================================================
#define PJ_AHI 0
#define PJ_ALO 16384
#define PJ_BHI 32768
#define PJ_BLO 49152
#define PJ_STAGE 65536
#define PJ_SMEM (2 * PJ_STAGE)

__global__ void __launch_bounds__(512, 1) proj_mma_kernel(
    const float* __restrict__ keys, const float* __restrict__ values)
{
    const int dt = blockIdx.x;
    const int b  = blockIdx.y;
    const int w  = blockIdx.z;

    const float* __restrict__ X = (w ? values : keys) + (size_t)b * Nn * Dn + dt * 128;
    const uint32_t* __restrict__ PTh = g_PTh + (size_t)w * Kn * (Nn / 2);
    const uint32_t* __restrict__ PTl = g_PTl + (size_t)w * Kn * (Nn / 2);
    float* __restrict__ Cg = (w ? g_vp : g_kp) + (size_t)b * Kn * Dn + dt * 128;

    extern __shared__ __align__(1024) unsigned char dsm[];
    const uint32_t sbase = smem_u32(dsm);

    const int tid  = threadIdx.x;
    const int wid  = tid >> 5, lane = tid & 31;
    const int warp_m = (wid >> 2) * 32;
    const int warp_d = (wid & 3) * 32;

    float acc[2][4][4];
    #pragma unroll
    for (int i = 0; i < 2; i++)
        #pragma unroll
        for (int j = 0; j < 4; j++)
            #pragma unroll
            for (int q = 0; q < 4; q++) acc[i][j][q] = 0.0f;

    uint4  pA[4];
    float4 pB[4];

    #pragma unroll
    for (int u = 0; u < 2; u++) {
        int idx = tid + 512 * u;
        int row = idx >> 3, c8 = idx & 7;
        size_t o = (size_t)row * (Nn / 2) + c8 * 4;
        pA[u]     = *(const uint4*)&PTh[o];
        pA[2 + u] = *(const uint4*)&PTl[o];
    }
    #pragma unroll
    for (int u = 0; u < 4; u++) {
        int idx = tid + 512 * u;
        int row = idx >> 5, c4 = idx & 31;
        pB[u] = *(const float4*)&X[(size_t)row * Dn + c4 * 4];
    }

    for (int c = 0; c < 64; ++c) {
        unsigned char* st = dsm + (c & 1) * PJ_STAGE;

        #pragma unroll
        for (int u = 0; u < 2; u++) {
            int idx = tid + 512 * u;
            int row = idx >> 3, c8 = idx & 7;
            uint32_t off = SWZ128((uint32_t)(row * 128 + c8 * 16));
            *(uint4*)(st + PJ_AHI + off) = pA[u];
            *(uint4*)(st + PJ_ALO + off) = pA[2 + u];
        }
        #pragma unroll
        for (int u = 0; u < 4; u++) {
            int idx = tid + 512 * u;
            int row = idx >> 5, c4 = idx & 31;
            uint2 hh, ll;
            split4h(pB[u], 1.0f, hh, ll);
            uint32_t off = SWZ256((uint32_t)(row * 256 + c4 * 8));
            *(uint2*)(st + PJ_BHI + off) = hh;
            *(uint2*)(st + PJ_BLO + off) = ll;
        }
        __syncthreads();

        if (c < 63) {
            int nb = (c + 1) * 64;
            #pragma unroll
            for (int u = 0; u < 2; u++) {
                int idx = tid + 512 * u;
                int row = idx >> 3, c8 = idx & 7;
                size_t o = (size_t)row * (Nn / 2) + (nb >> 1) + c8 * 4;
                pA[u]     = *(const uint4*)&PTh[o];
                pA[2 + u] = *(const uint4*)&PTl[o];
            }
            #pragma unroll
            for (int u = 0; u < 4; u++) {
                int idx = tid + 512 * u;
                int row = idx >> 5, c4 = idx & 31;
                pB[u] = *(const float4*)&X[(size_t)(nb + row) * Dn + c4 * 4];
            }
        }

        const uint32_t sA = sbase + (c & 1) * PJ_STAGE;
        const uint32_t sB = sA + PJ_BHI;
        #pragma unroll
        for (int ks = 0; ks < 4; ks++) {
            uint32_t ah[2][4], al[2][4];
            #pragma unroll
            for (int mi = 0; mi < 2; mi++) {
                uint32_t off = SWZ128((uint32_t)((warp_m + mi * 16 + (lane & 15)) * 128
                                                 + ks * 32 + (lane >> 4) * 16));
                LDSM4(ah[mi], sA + PJ_AHI + off);
                LDSM4(al[mi], sA + PJ_ALO + off);
            }
            #pragma unroll
            for (int g2 = 0; g2 < 2; g2++) {
                uint32_t offb = SWZ256((uint32_t)((ks * 16 + (lane & 15)) * 256
                                                  + warp_d * 2 + g2 * 32 + (lane >> 4) * 16));
                uint32_t bh[4], bl[4];
                LDSM4T(bh, sB + offb);
                LDSM4T(bl, sB + (PJ_BLO - PJ_BHI) + offb);
                #pragma unroll
                for (int mi = 0; mi < 2; mi++) {
                    #pragma unroll
                    for (int jj = 0; jj < 2; jj++) {
                        float* cc = acc[mi][g2 * 2 + jj];
                        MMA_F16(cc, ah[mi], bh[jj * 2], bh[jj * 2 + 1]);
                        MMA_F16(cc, ah[mi], bl[jj * 2], bl[jj * 2 + 1]);
                        MMA_F16(cc, al[mi], bh[jj * 2], bh[jj * 2 + 1]);
                    }
                }
            }
        }
        __syncthreads();
    }

    #pragma unroll
    for (int mi = 0; mi < 2; mi++) {
        #pragma unroll
        for (int j = 0; j < 4; j++) {
            int row = warp_m + mi * 16 + (lane >> 2);
            int col = warp_d + j * 8 + (lane & 3) * 2;
            *(float2*)&Cg[(size_t)row * Dn + col] =
                make_float2(acc[mi][j][0], acc[mi][j][1]);
            *(float2*)&Cg[(size_t)(row + 8) * Dn + col] =
                make_float2(acc[mi][j][2], acc[mi][j][3]);
        }
    }
}

// ============================================================================
// Kernel 2: tensor-core attention, fp16 limbs.
//   GEMM1: 3-pass (Q,K 2-limb).  Softmax (max-sub), P stored SINGLE fp16.
//   GEMM2: 2-pass (P single x V 2-limb).
// ============================================================================
#define AT_QHI  0
#define AT_QLO  16384
#define AT_KHI  32768
#define AT_KLO  49152
#define AT_PHI  0
#define AT_VHI  65536
#define AT_VLO  81920
#define AT_SMAX 98304
#define AT_SSUM 99328
#define AT_SMEM 100352

__global__ void __launch_bounds__(256, 2) attn_mma_kernel(
    const float* __restrict__ qg, float* __restrict__ outg)
{
    const int nt = blockIdx.x;
    const int h  = blockIdx.y;
    const int b  = blockIdx.z;

    extern __shared__ __align__(1024) unsigned char smb[];
    const uint32_t sbase = smem_u32(smb);
    float* smax = (float*)(smb + AT_SMAX);
    float* ssum = (float*)(smb + AT_SSUM);

    const int tid  = threadIdx.x;
    const int wid  = tid >> 5, lane = tid & 31;
    const int g    = lane >> 2, tk = lane & 3;
    const int wm   = (wid >> 1) * 32;
    const int kh   = wid & 1;

    // ---- load + split Q (x0.125), KK, VV into smem ----
    {
        const size_t qbase = ((size_t)b * Nn + (size_t)nt * 128) * Dn + h * 64;
        const size_t kbase = (size_t)b * Kn * Dn + h * 64;
        #pragma unroll
        for (int t = 0; t < 8; t++) {
            int idx = tid + 256 * t;
            int row = idx >> 4, c4 = idx & 15;
            size_t go = (size_t)row * Dn + c4 * 4;
            uint32_t off = SWZ128((uint32_t)(row * 128 + c4 * 8));
            uint2 hh, ll;
            split4h(*(const float4*)&qg[qbase + go], 0.125f, hh, ll);
            *(uint2*)(smb + AT_QHI + off) = hh;
            *(uint2*)(smb + AT_QLO + off) = ll;
            split4h(*(const float4*)&g_kp[kbase + go], 1.0f, hh, ll);
            *(uint2*)(smb + AT_KHI + off) = hh;
            *(uint2*)(smb + AT_KLO + off) = ll;
            split4h(*(const float4*)&g_vp[kbase + go], 1.0f, hh, ll);
            *(uint2*)(smb + AT_VHI + off) = hh;
            *(uint2*)(smb + AT_VLO + off) = ll;
        }
    }
    __syncthreads();

    // ---- GEMM1: dots[128n x 128k]; warp tile 32n x 64k; 3-pass ----
    float acc[2][8][4];
    #pragma unroll
    for (int i = 0; i < 2; i++)
        #pragma unroll
        for (int j = 0; j < 8; j++)
            #pragma unroll
            for (int q = 0; q < 4; q++) acc[i][j][q] = 0.0f;

    {
        const int wk = kh * 64;
        #pragma unroll
        for (int ks = 0; ks < 4; ks++) {
            uint32_t ah[2][4], al[2][4];
            #pragma unroll
            for (int mi = 0; mi < 2; mi++) {
                uint32_t off = SWZ128((uint32_t)((wm + mi * 16 + (lane & 15)) * 128
                                                 + ks * 32 + (lane >> 4) * 16));
                LDSM4(ah[mi], sbase + AT_QHI + off);
                LDSM4(al[mi], sbase + AT_QLO + off);
            }
            #pragma unroll
            for (int jj = 0; jj < 4; jj++) {
                uint32_t offb = SWZ128((uint32_t)((wk + jj * 16 + (lane & 15)) * 128
                                                  + ks * 32 + (lane >> 4) * 16));
                uint32_t bh[4], bl[4];
                LDSM4(bh, sbase + AT_KHI + offb);
                LDSM4(bl, sbase + AT_KLO + offb);
                // non-trans B pairing: tile(2jj)=(r0,r2), tile(2jj+1)=(r1,r3)
                #pragma unroll
                for (int mi = 0; mi < 2; mi++) {
                    float* c0 = acc[mi][jj * 2];
                    MMA_F16(c0, ah[mi], bh[0], bh[2]);
                    MMA_F16(c0, ah[mi], bl[0], bl[2]);
                    MMA_F16(c0, al[mi], bh[0], bh[2]);
                    float* c1v = acc[mi][jj * 2 + 1];
                    MMA_F16(c1v, ah[mi], bh[1], bh[3]);
                    MMA_F16(c1v, ah[mi], bl[1], bl[3]);
                    MMA_F16(c1v, al[mi], bh[1], bh[3]);
                }
            }
        }
    }

    // ---- softmax part 1: row max ----
    #pragma unroll
    for (int mi = 0; mi < 2; mi++) {
        #pragma unroll
        for (int h2 = 0; h2 < 2; h2++) {
            float m = acc[mi][0][h2 * 2];
            #pragma unroll
            for (int j = 0; j < 8; j++)
                m = fmaxf(m, fmaxf(acc[mi][j][h2 * 2], acc[mi][j][h2 * 2 + 1]));
            m = fmaxf(m, __shfl_xor_sync(0xffffffffu, m, 1));
            m = fmaxf(m, __shfl_xor_sync(0xffffffffu, m, 2));
            if (tk == 0) smax[(wm + mi * 16 + g + h2 * 8) * 2 + kh] = m;
        }
    }
    __syncthreads();

    // ---- softmax part 2: exp, write SINGLE fp16 P; sum from rounded P ----
    #pragma unroll
    for (int mi = 0; mi < 2; mi++) {
        #pragma unroll
        for (int h2 = 0; h2 < 2; h2++) {
            int row = wm + mi * 16 + g + h2 * 8;
            float M = fmaxf(smax[row * 2], smax[row * 2 + 1]);
            float s = 0.0f;
            #pragma unroll
            for (int j = 0; j < 8; j++) {
                float x0 = __expf(acc[mi][j][h2 * 2]     - M);
                float x1 = __expf(acc[mi][j][h2 * 2 + 1] - M);
                uint32_t ph = cvt2h(x1, x0);
                // accumulate the ROUNDED weights so normalization cancels
                // the common-mode fp16 rounding error
                s += f16lo(ph) + f16hi(ph);
                uint32_t off = SWZ256((uint32_t)(row * 256 + kh * 128 + j * 16 + tk * 4));
                *(uint32_t*)(smb + AT_PHI + off) = ph;
            }
            s += __shfl_xor_sync(0xffffffffu, s, 1);
            s += __shfl_xor_sync(0xffffffffu, s, 2);
            if (tk == 0) ssum[row * 2 + kh] = s;
        }
    }
    __syncthreads();

    // ---- GEMM2: out = P . VV; 2-pass (P single, V 2-limb) ----
    float o[2][4][4];
    #pragma unroll
    for (int i = 0; i < 2; i++)
        #pragma unroll
        for (int j = 0; j < 4; j++)
            #pragma unroll
            for (int q = 0; q < 4; q++) o[i][j][q] = 0.0f;

    {
        const int wdh = kh * 32;
        #pragma unroll
        for (int ks = 0; ks < 8; ks++) {
            uint32_t ah[2][4];
            #pragma unroll
            for (int mi = 0; mi < 2; mi++) {
                uint32_t off = SWZ256((uint32_t)((wm + mi * 16 + (lane & 15)) * 256
                                                 + ks * 32 + (lane >> 4) * 16));
                LDSM4(ah[mi], sbase + AT_PHI + off);
            }
            #pragma unroll
            for (int g2 = 0; g2 < 2; g2++) {
                uint32_t offb = SWZ128((uint32_t)((ks * 16 + (lane & 15)) * 128
                                                  + wdh * 2 + g2 * 32 + (lane >> 4) * 16));
                uint32_t bh[4], bl[4];
                LDSM4T(bh, sbase + AT_VHI + offb);
                LDSM4T(bl, sbase + AT_VLO + offb);
                // trans B pairing: tile(g2*2)=(r0,r1), tile(g2*2+1)=(r2,r3)
                #pragma unroll
                for (int mi = 0; mi < 2; mi++) {
                    #pragma unroll
                    for (int jj = 0; jj < 2; jj++) {
                        float* cc = o[mi][g2 * 2 + jj];
                        MMA_F16(cc, ah[mi], bh[jj * 2], bh[jj * 2 + 1]);
                        MMA_F16(cc, ah[mi], bl[jj * 2], bl[jj * 2 + 1]);
                    }
                }
            }
        }
    }

    // ---- epilogue: normalize by 1/rowsum, store ----
    {
        const int wdh = kh * 32;
        const size_t obase = ((size_t)b * Nn + (size_t)nt * 128) * Dn + h * 64;
        #pragma unroll
        for (int mi = 0; mi < 2; mi++) {
            int r0 = wm + mi * 16 + g;
            int r1 = r0 + 8;
            float ri0 = 1.0f / (ssum[r0 * 2] + ssum[r0 * 2 + 1]);
            float ri1 = 1.0f / (ssum[r1 * 2] + ssum[r1 * 2 + 1]);
            #pragma unroll
            for (int j = 0; j < 4; j++) {
                int col = wdh + j * 8 + tk * 2;
                *(float2*)&outg[obase + (size_t)r0 * Dn + col] =
                    make_float2(o[mi][j][0] * ri0, o[mi][j][1] * ri0);
                *(float2*)&outg[obase + (size_t)r1 * Dn + col] =
                    make_float2(o[mi][j][2] * ri1, o[mi][j][3] * ri1);
            }
        }
    }
}

// ============================================================================
// Launch
// ============================================================================
extern "C" void kernel_launch(void* const* d_in, const int* in_sizes, int n_in,
                              void* d_out, int out_size)
{
    const float* q      = (const float*)d_in[0];
    const float* keys   = (const float*)d_in[1];
    const float* values = (const float*)d_in[2];
    const float* pk     = (const float*)d_in[3];
    const float* pv     = (const float*)d_in[4];
    float* out = (float*)d_out;

    cudaFuncSetAttribute(proj_mma_kernel,
                         cudaFuncAttributeMaxDynamicSharedMemorySize, PJ_SMEM);
    cudaFuncSetAttribute(attn_mma_kernel,
                         cudaFuncAttributeMaxDynamicSharedMemorySize, AT_SMEM);

    ptrans_kernel<<<dim3(Nn / 32, 2), 256>>>(pk, pv);
    proj_mma_kernel<<<dim3(8, Bsz, 2), 512, PJ_SMEM>>>(keys, values);
    attn_mma_kernel<<<dim3(Nn / 128, Hn, Bsz), 256, AT_SMEM>>>(q, out);
}